// round 4
// baseline (speedup 1.0000x reference)
#include <cuda_runtime.h>
#include <cuda_bf16.h>

// ---------------- problem constants ----------------
#define NN    20000            // nodes
#define NE    320000           // edges (without self loops)
#define ET    (NE + NN)        // edges + self loops = 340000
#define FIN   256              // input channels
#define HID   32               // hidden per head
#define HEADS 8
#define F1    256              // HEADS*HID
#define NC    16               // classes
#define NEGSL 0.2f
#define EPSF  1e-16f

// ---------------- device scratch (no allocations allowed) ----------------
__device__ float g_h1  [NN * F1];      // x @ W1
__device__ float g_agg1[NN * F1];      // layer1 aggregate -> elu in place
__device__ float g_as1 [NN * HEADS];
__device__ float g_ad1 [NN * HEADS];
__device__ float g_m1  [NN * HEADS];
__device__ float g_den1[NN * HEADS];
__device__ float g_ex1 [ET * HEADS];   // logits, then exp()
__device__ float g_z2  [NN * NC];      // h @ W2
__device__ float g_as2 [NN];
__device__ float g_ad2 [NN];
__device__ float g_m2  [NN];
__device__ float g_den2[NN];
__device__ float g_ex2 [ET];

// ---------------- helpers ----------------
__device__ __forceinline__ void atomicMaxF(float* addr, float v) {
    // monotone float max via int/uint ordering trick; init value must be -inf
    if (v >= 0.0f) atomicMax(reinterpret_cast<int*>(addr), __float_as_int(v));
    else           atomicMin(reinterpret_cast<unsigned int*>(addr), __float_as_uint(v));
}

__device__ __forceinline__ void redAdd4(float* p, float4 v) {
#if defined(__CUDA_ARCH__) && (__CUDA_ARCH__ >= 900)
    atomicAdd(reinterpret_cast<float4*>(p), v);   // RED.128 on sm_90+
#else
    atomicAdd(p + 0, v.x); atomicAdd(p + 1, v.y);
    atomicAdd(p + 2, v.z); atomicAdd(p + 3, v.w);
#endif
}

// ---------------- init ----------------
__global__ void k_init(float* __restrict__ out) {
    int i = blockIdx.x * blockDim.x + threadIdx.x;
    const float ninf = __int_as_float(0xff800000);
    if (i < NN * F1)    g_agg1[i] = 0.0f;
    if (i < NN * HEADS) { g_m1[i] = ninf; g_den1[i] = 0.0f; }
    if (i < NN)         { g_m2[i] = ninf; g_den2[i] = 0.0f; }
    if (i < NN * NC)    out[i] = 0.0f;
}

// ---------------- GEMM1: g_h1[NN,256] = x[NN,256] @ W1[256,256] ----------------
// 64x64 tile, BK=16, 256 threads, 4x4 per thread
__global__ void k_gemm1(const float* __restrict__ A, const float* __restrict__ B) {
    __shared__ float As[16][64];
    __shared__ float Bs[16][64];
    const int t  = threadIdx.x;
    const int tx = t & 15, ty = t >> 4;
    const int rowBase = blockIdx.y * 64;
    const int colBase = blockIdx.x * 64;
    const int arow = t >> 2,  acol = (t & 3) * 4;
    const int brow = t >> 4,  bcol = (t & 15) * 4;

    float acc[4][4];
#pragma unroll
    for (int i = 0; i < 4; i++)
#pragma unroll
        for (int j = 0; j < 4; j++) acc[i][j] = 0.0f;

    for (int k0 = 0; k0 < 256; k0 += 16) {
        float4 av = make_float4(0.f, 0.f, 0.f, 0.f);
        int grow = rowBase + arow;
        if (grow < NN) av = *reinterpret_cast<const float4*>(A + grow * 256 + k0 + acol);
        As[acol + 0][arow] = av.x;
        As[acol + 1][arow] = av.y;
        As[acol + 2][arow] = av.z;
        As[acol + 3][arow] = av.w;
        float4 bv = *reinterpret_cast<const float4*>(B + (k0 + brow) * 256 + colBase + bcol);
        *reinterpret_cast<float4*>(&Bs[brow][bcol]) = bv;
        __syncthreads();
#pragma unroll
        for (int k = 0; k < 16; k++) {
            float a0 = As[k][ty * 4 + 0];
            float a1 = As[k][ty * 4 + 1];
            float a2 = As[k][ty * 4 + 2];
            float a3 = As[k][ty * 4 + 3];
            float4 b = *reinterpret_cast<float4*>(&Bs[k][tx * 4]);
            acc[0][0] += a0 * b.x; acc[0][1] += a0 * b.y; acc[0][2] += a0 * b.z; acc[0][3] += a0 * b.w;
            acc[1][0] += a1 * b.x; acc[1][1] += a1 * b.y; acc[1][2] += a1 * b.z; acc[1][3] += a1 * b.w;
            acc[2][0] += a2 * b.x; acc[2][1] += a2 * b.y; acc[2][2] += a2 * b.z; acc[2][3] += a2 * b.w;
            acc[3][0] += a3 * b.x; acc[3][1] += a3 * b.y; acc[3][2] += a3 * b.z; acc[3][3] += a3 * b.w;
        }
        __syncthreads();
    }
#pragma unroll
    for (int i = 0; i < 4; i++) {
        int r = rowBase + ty * 4 + i;
        if (r < NN) {
            float4 v = make_float4(acc[i][0], acc[i][1], acc[i][2], acc[i][3]);
            *reinterpret_cast<float4*>(g_h1 + r * 256 + colBase + tx * 4) = v;
        }
    }
}

// ---------------- attention scalars layer1: warp per node ----------------
__global__ void k_att1(const float* __restrict__ att_s, const float* __restrict__ att_d) {
    int node = blockIdx.x * 8 + (threadIdx.x >> 5);
    if (node >= NN) return;
    int lane = threadIdx.x & 31;
    const float* hr = g_h1 + node * F1;
#pragma unroll
    for (int h = 0; h < HEADS; h++) {
        float v = hr[h * 32 + lane];
        float s = v * att_s[h * 32 + lane];
        float d = v * att_d[h * 32 + lane];
#pragma unroll
        for (int o = 16; o; o >>= 1) {
            s += __shfl_xor_sync(0xffffffffu, s, o);
            d += __shfl_xor_sync(0xffffffffu, d, o);
        }
        if (lane == 0) { g_as1[node * 8 + h] = s; g_ad1[node * 8 + h] = d; }
    }
}

// ---------------- layer1 edge pass 1: logit + segment max ----------------
__global__ void k_max1(const int* __restrict__ src, const int* __restrict__ dst,
                       const float* __restrict__ ew) {
    int idx = blockIdx.x * blockDim.x + threadIdx.x;
    if (idx >= ET * HEADS) return;
    int e = idx >> 3, h = idx & 7;
    int s, d; float w;
    if (e < NE) { s = src[e]; d = dst[e]; w = ew[e]; }
    else        { s = d = e - NE; w = 1.0f; }
    float v = g_as1[s * 8 + h] + g_ad1[d * 8 + h];
    v = (v > 0.0f) ? v : NEGSL * v;
    v *= w;
    g_ex1[idx] = v;                    // cache logit
    atomicMaxF(&g_m1[d * 8 + h], v);
}

// ---------------- layer1 edge pass 2: exp + denom ----------------
__global__ void k_exp1(const int* __restrict__ dst) {
    int idx = blockIdx.x * blockDim.x + threadIdx.x;
    if (idx >= ET * HEADS) return;
    int e = idx >> 3, h = idx & 7;
    int d = (e < NE) ? dst[e] : (e - NE);
    float ex = expf(g_ex1[idx] - g_m1[d * 8 + h]);
    g_ex1[idx] = ex;
    atomicAdd(&g_den1[d * 8 + h], ex);
}

// ---------------- layer1 edge pass 3: weighted aggregate (warp per edge) ----
__global__ void k_agg1(const int* __restrict__ src, const int* __restrict__ dst) {
    int e = (blockIdx.x * blockDim.x + threadIdx.x) >> 5;
    if (e >= ET) return;
    int lane = threadIdx.x & 31;
    int s, d;
    if (e < NE) { s = src[e]; d = dst[e]; }
    else        { s = d = e - NE; }
    int h  = lane >> 2;            // head 0..7
    int fo = (lane & 3) << 3;      // 0,8,16,24 within head
    float alpha = g_ex1[e * 8 + h] / (g_den1[d * 8 + h] + EPSF);
    const float4* hs = reinterpret_cast<const float4*>(g_h1 + s * 256 + h * 32 + fo);
    float4 v0 = hs[0];
    float4 v1 = hs[1];
    float* ag = g_agg1 + d * 256 + h * 32 + fo;
    redAdd4(ag,     make_float4(alpha * v0.x, alpha * v0.y, alpha * v0.z, alpha * v0.w));
    redAdd4(ag + 4, make_float4(alpha * v1.x, alpha * v1.y, alpha * v1.z, alpha * v1.w));
}

// ---------------- bias + elu (in place on g_agg1) ----------------
__global__ void k_elu(const float* __restrict__ b1) {
    int i = blockIdx.x * blockDim.x + threadIdx.x;
    if (i >= NN * F1) return;
    float v = g_agg1[i] + b1[i & 255];
    g_agg1[i] = (v > 0.0f) ? v : (expf(v) - 1.0f);
}

// ---------------- GEMM2: g_z2[NN,16] = g_agg1[NN,256] @ W2[256,16] ----------
__global__ void k_gemm2(const float* __restrict__ W2) {
    __shared__ float Ws[256][16];
    int t = threadIdx.x;
    for (int i = t; i < 256 * 16; i += 256) Ws[i >> 4][i & 15] = W2[i];
    __syncthreads();
    int n = blockIdx.x * 16 + (t >> 4);   // 20000 = 16 * 1250 exact
    int c = t & 15;
    const float* a = g_agg1 + n * 256;
    float sum = 0.0f;
#pragma unroll 8
    for (int k = 0; k < 256; k++) sum += a[k] * Ws[k][c];
    g_z2[n * 16 + c] = sum;
}

// ---------------- attention scalars layer2 ----------------
__global__ void k_att2(const float* __restrict__ att_s, const float* __restrict__ att_d) {
    int n = blockIdx.x * blockDim.x + threadIdx.x;
    if (n >= NN) return;
    const float* z = g_z2 + n * 16;
    float s = 0.0f, d = 0.0f;
#pragma unroll
    for (int c = 0; c < 16; c++) { float v = z[c]; s += v * att_s[c]; d += v * att_d[c]; }
    g_as2[n] = s; g_ad2[n] = d;
}

// ---------------- layer2 edge pass 1 ----------------
__global__ void k_max2(const int* __restrict__ src, const int* __restrict__ dst,
                       const float* __restrict__ ew) {
    int e = blockIdx.x * blockDim.x + threadIdx.x;
    if (e >= ET) return;
    int s, d; float w;
    if (e < NE) { s = src[e]; d = dst[e]; w = ew[e]; }
    else        { s = d = e - NE; w = 1.0f; }
    float v = g_as2[s] + g_ad2[d];
    v = (v > 0.0f) ? v : NEGSL * v;
    v *= w;
    g_ex2[e] = v;
    atomicMaxF(&g_m2[d], v);
}

// ---------------- layer2 edge pass 2 ----------------
__global__ void k_exp2(const int* __restrict__ dst) {
    int e = blockIdx.x * blockDim.x + threadIdx.x;
    if (e >= ET) return;
    int d = (e < NE) ? dst[e] : (e - NE);
    float ex = expf(g_ex2[e] - g_m2[d]);
    g_ex2[e] = ex;
    atomicAdd(&g_den2[d], ex);
}

// ---------------- layer2 edge pass 3: 4 threads per edge (float4 each) -----
__global__ void k_agg2(const int* __restrict__ src, const int* __restrict__ dst,
                       float* __restrict__ out) {
    int idx = blockIdx.x * blockDim.x + threadIdx.x;
    if (idx >= ET * 4) return;
    int e = idx >> 2, q = idx & 3;
    int s, d;
    if (e < NE) { s = src[e]; d = dst[e]; }
    else        { s = d = e - NE; }
    float alpha = g_ex2[e] / (g_den2[d] + EPSF);
    float4 v = *reinterpret_cast<const float4*>(g_z2 + s * 16 + q * 4);
    redAdd4(out + d * 16 + q * 4,
            make_float4(alpha * v.x, alpha * v.y, alpha * v.z, alpha * v.w));
}

// ---------------- final bias ----------------
__global__ void k_bias2(float* __restrict__ out, const float* __restrict__ b2) {
    int i = blockIdx.x * blockDim.x + threadIdx.x;
    if (i >= NN * NC) return;
    out[i] += b2[i & 15];
}

// ---------------- launch ----------------
extern "C" void kernel_launch(void* const* d_in, const int* in_sizes, int n_in,
                              void* d_out, int out_size) {
    const float* x    = (const float*)d_in[0];
    const int*   ei   = (const int*)  d_in[1];
    const float* ew   = (const float*)d_in[2];
    const float* W1   = (const float*)d_in[3];
    const float* as1  = (const float*)d_in[4];
    const float* ad1  = (const float*)d_in[5];
    const float* b1   = (const float*)d_in[6];
    const float* W2   = (const float*)d_in[7];
    const float* as2  = (const float*)d_in[8];
    const float* ad2  = (const float*)d_in[9];
    const float* b2   = (const float*)d_in[10];
    float* out = (float*)d_out;
    const int* src = ei;
    const int* dst = ei + NE;

    const int TB = 256;

    k_init<<<(NN * F1 + TB - 1) / TB, TB>>>(out);

    dim3 g1(256 / 64, (NN + 63) / 64);
    k_gemm1<<<g1, TB>>>(x, W1);

    k_att1<<<(NN + 7) / 8, TB>>>(as1, ad1);

    k_max1<<<(ET * HEADS + TB - 1) / TB, TB>>>(src, dst, ew);
    k_exp1<<<(ET * HEADS + TB - 1) / TB, TB>>>(dst);
    k_agg1<<<(ET * 32 + TB - 1) / TB, TB>>>(src, dst);

    k_elu<<<(NN * F1 + TB - 1) / TB, TB>>>(b1);

    k_gemm2<<<NN / 16, TB>>>(W2);
    k_att2<<<(NN + TB - 1) / TB, TB>>>(as2, ad2);

    k_max2<<<(ET + TB - 1) / TB, TB>>>(src, dst, ew);
    k_exp2<<<(ET + TB - 1) / TB, TB>>>(dst);
    k_agg2<<<(ET * 4 + TB - 1) / TB, TB>>>(src, dst, out);

    k_bias2<<<(NN * NC + TB - 1) / TB, TB>>>(out, b2);
}